// round 7
// baseline (speedup 1.0000x reference)
#include <cuda_runtime.h>
#include <cuda_fp16.h>
#include <cstdint>

#define TT 16384
#define DD 2048
#define EE 64
#define BM 128
#define NT 512
#define NCH 32                 // K=32 chunks; each warp covers one K-half (1024)

#define STAGES 4
#define STAGE_BYTES 49152      // 2 x-halves (16KB each, f32) + 2 B-halves (8KB each)
#define XHALF_BYTES 16384
#define B_OFF 32768
#define BHALF_BYTES 8192
#define SMEM_BYTES (STAGES * STAGE_BYTES)    // 196608

// epilogue overlay (u32 offsets into the same smem)
#define SC_STRIDE 66
#define BOARD_U32 (BM * SC_STRIDE)           // 8448
#define CNT (2 * BOARD_U32)
#define I1A (CNT + 64)
#define I2A (I1A + 128)
#define G1A (I2A + 128)
#define G2A (G1A + 128)

// ---- output layout (floats) ----
#define IDX_OFF  ((size_t)TT * EE)
#define GATE_OFF (IDX_OFF + 2 * (size_t)TT)
#define ACT_OFF  (GATE_OFF + 2 * (size_t)TT)
#define FULL_OUT (ACT_OFF + EE)

#define SWZ(o) ((o) ^ (((o) >> 3) & 0x70))

// w pre-split to fp16 hi/lo, fragment-major: [k16-step 128][nb 8][lane 32] uint4
// v = {b0_hi, b1_hi, b0_lo, b1_lo} for mma.m16n8k16 B fragment
__device__ uint4 g_w_frag[128 * 8 * 32];

__device__ __forceinline__ uint32_t packh2(__half a, __half b) {
    uint32_t u;
    asm("mov.b32 %0, {%1, %2};" : "=r"(u) : "h"(__half_as_ushort(a)), "h"(__half_as_ushort(b)));
    return u;
}
__device__ __forceinline__ void split_f16(float x, __half& h, __half& l) {
    h = __float2half_rn(x);
    l = __float2half_rn(x - __half2float(h));
}
__device__ __forceinline__ uint32_t split2(float2 v, uint32_t& lo) {
    __half hx, lx, hy, ly;
    split_f16(v.x, hx, lx);
    split_f16(v.y, hy, ly);
    lo = packh2(lx, ly);
    return packh2(hx, hy);
}
__device__ __forceinline__ void mma_f16(float* d, const uint32_t* a, uint32_t b0, uint32_t b1) {
    asm volatile(
        "mma.sync.aligned.m16n8k16.row.col.f32.f16.f16.f32 "
        "{%0,%1,%2,%3}, {%4,%5,%6,%7}, {%8,%9}, {%0,%1,%2,%3};"
        : "+f"(d[0]), "+f"(d[1]), "+f"(d[2]), "+f"(d[3])
        : "r"(a[0]), "r"(a[1]), "r"(a[2]), "r"(a[3]), "r"(b0), "r"(b1));
}
__device__ __forceinline__ void cp16(uint32_t dst, const void* src) {
    asm volatile("cp.async.cg.shared.global [%0], [%1], 16;" :: "r"(dst), "l"(src));
}
#define CP_COMMIT() asm volatile("cp.async.commit_group;" ::: "memory")
#define CP_WAIT2()  asm volatile("cp.async.wait_group 2;" ::: "memory")

// ======================= prep: w -> fragment-major fp16 hi/lo =======================
__global__ void prep_kernel(const float* __restrict__ w, float* __restrict__ out, int we) {
    int t = blockIdx.x * 256 + threadIdx.x;   // 32768 threads
    int ks = t >> 8, rem = t & 255, nb = rem >> 5, l = rem & 31;
    int n = nb * 8 + (l >> 2), tig = l & 3;
    int k0 = ks * 16 + 2 * tig, k1 = k0 + 8;
    float w00 = w[(size_t)k0 * EE + n],       w01 = w[(size_t)(k0 + 1) * EE + n];
    float w10 = w[(size_t)k1 * EE + n],       w11 = w[(size_t)(k1 + 1) * EE + n];
    __half h00, l00, h01, l01, h10, l10, h11, l11;
    split_f16(w00, h00, l00); split_f16(w01, l01, l01), split_f16(w01, h01, l01);
    split_f16(w10, h10, l10); split_f16(w11, h11, l11);
    uint4 v;
    v.x = packh2(h00, h01);
    v.y = packh2(h10, h11);
    v.z = packh2(l00, l01);
    v.w = packh2(l10, l11);
    g_w_frag[t] = v;
    if (we && t < EE) out[ACT_OFF + t] = 0.0f;
}

// ======================= main kernel =======================
__global__ __launch_bounds__(NT, 1)
void router_mma_kernel(const float* __restrict__ x,
                       const float* __restrict__ noise,
                       float* __restrict__ out,
                       int write_extras) {
    extern __shared__ char smem[];
    uint32_t smb;
    asm("{ .reg .u64 t; cvta.to.shared.u64 t, %1; cvt.u32.u64 %0, t; }" : "=r"(smb) : "l"(smem));

    const int tid = threadIdx.x;
    const int wid = tid >> 5;
    const int lid = tid & 31;
    const int s   = wid & 1;           // K half
    const int rb  = (wid >> 1) * 16;   // 16 rows per warp
    const int g   = lid >> 2;
    const int t4  = lid & 3;
    const int row0 = blockIdx.x * BM;

    // loader mapping (per thread, fixed)
    const int lh   = tid >> 8;         // loader half
    const int lf   = tid & 255;
    const int lr   = lf >> 1;          // x row 0..127
    const int lkc0 = (lf & 1) * 4;     // first 16B chunk (of 8 per 128B row-chunk)
    const float* lx = x + (size_t)(row0 + lr) * DD + lh * 1024 + lkc0 * 4;
    const uint32_t lxd = smb + lh * XHALF_BYTES;
    const uint4* lb = g_w_frag + lf;
    const uint32_t lbd = smb + B_OFF + lh * BHALF_BYTES + lf * 16;

    float acc[8][4];
#pragma unroll
    for (int nb = 0; nb < 8; nb++)
#pragma unroll
        for (int i = 0; i < 4; i++) acc[nb][i] = 0.0f;

    // ---- prologue: issue stages 0..2 ----
#pragma unroll
    for (int p = 0; p < 3; p++) {
        const uint32_t sb = p * STAGE_BYTES;
#pragma unroll
        for (int j = 0; j < 4; j++)
            cp16(sb + lxd + SWZ((uint32_t)(lr * 128 + (lkc0 + j) * 16)), lx + p * 32 + j * 4);
        const uint4* bs = lb + (size_t)(lh * 64 + p * 2) * 256;
        cp16(sb + lbd, bs);
        cp16(sb + lbd + 256 * 16, bs + 256);
        CP_COMMIT();
    }

    for (int c = 0; c < NCH; ++c) {
        CP_WAIT2();
        __syncthreads();

        // issue chunk c+3 into stage (c+3)%4 (readers of that stage finished at iter c-1)
        if (c + 3 < NCH) {
            const int cn = c + 3;
            const uint32_t sb = (cn & 3) * STAGE_BYTES;
#pragma unroll
            for (int j = 0; j < 4; j++)
                cp16(sb + lxd + SWZ((uint32_t)(lr * 128 + (lkc0 + j) * 16)), lx + cn * 32 + j * 4);
            const uint4* bs = lb + (size_t)(lh * 64 + cn * 2) * 256;
            cp16(sb + lbd, bs);
            cp16(sb + lbd + 256 * 16, bs + 256);
        }
        CP_COMMIT();

        // ---- consume stage c%4 ----
        const char* xa = smem + (c & 3) * STAGE_BYTES + s * XHALF_BYTES;
        const uint4* Bs = (const uint4*)(smem + (c & 3) * STAGE_BYTES + B_OFF + s * BHALF_BYTES);
#pragma unroll
        for (int ks = 0; ks < 2; ks++) {
            uint4 bv[8];
#pragma unroll
            for (int nb = 0; nb < 8; nb++) bv[nb] = Bs[(ks * 8 + nb) * 32 + lid];

            const uint32_t ob = (uint32_t)((rb + g) * 128 + ks * 64 + t4 * 8);
            float2 av0 = *(const float2*)(xa + SWZ(ob));
            float2 av1 = *(const float2*)(xa + SWZ(ob + 1024));
            float2 av2 = *(const float2*)(xa + SWZ(ob + 32));
            float2 av3 = *(const float2*)(xa + SWZ(ob + 1024 + 32));

            uint32_t ah[4], al[4];
            ah[0] = split2(av0, al[0]);
            ah[1] = split2(av1, al[1]);
            ah[2] = split2(av2, al[2]);
            ah[3] = split2(av3, al[3]);

#pragma unroll
            for (int nb = 0; nb < 8; nb++) mma_f16(acc[nb], ah, bv[nb].x, bv[nb].y);  // h*h
#pragma unroll
            for (int nb = 0; nb < 8; nb++) mma_f16(acc[nb], ah, bv[nb].z, bv[nb].w);  // h*l
#pragma unroll
            for (int nb = 0; nb < 8; nb++) mma_f16(acc[nb], al, bv[nb].x, bv[nb].y);  // l*h
        }
    }

    // ================= epilogue =================
    __syncthreads();                       // everyone done reading stages
    uint32_t* smu = (uint32_t*)smem;
    float* sc0 = (float*)smu;              // board half 0: [128][66]
    float* sc1 = (float*)(smu + BOARD_U32);
    int*   counts = (int*)(smu + CNT);
    int*   i1a = (int*)(smu + I1A);
    int*   i2a = (int*)(smu + I2A);
    float* g1a = (float*)(smu + G1A);
    float* g2a = (float*)(smu + G2A);

    // scatter accumulators to this half's board
    {
        float* scb = s ? sc1 : sc0;
        const int r0 = rb + g;
#pragma unroll
        for (int nb = 0; nb < 8; nb++) {
            int cc = nb * 8 + t4 * 2;
            float2 v0; v0.x = acc[nb][0]; v0.y = acc[nb][1];
            float2 v1; v1.x = acc[nb][2]; v1.y = acc[nb][3];
            *(float2*)(scb + r0 * SC_STRIDE + cc)       = v0;
            *(float2*)(scb + (r0 + 8) * SC_STRIDE + cc) = v1;
        }
    }
    if (tid < EE) counts[tid] = 0;
    __syncthreads();

    // sum K-halves + noise (coalesced)
#pragma unroll
    for (int j = 0; j < 16; j++) {
        int flat = tid + NT * j;           // 8192 elems
        int r = flat >> 6, e = flat & 63;
        sc0[r * SC_STRIDE + e] = sc0[r * SC_STRIDE + e] + sc1[r * SC_STRIDE + e]
                               + noise[(size_t)row0 * EE + flat];
    }
    __syncthreads();

    // per-row top-2 + gates (renormalized top-2 softmax == sigmoid of score diff)
    if (tid < BM) {
        const int row = tid;
        const float* p = sc0 + row * SC_STRIDE;
        float m1 = -3.402823466e38f, m2 = -3.402823466e38f;
        int b1 = 0, b2 = 0;
#pragma unroll
        for (int e = 0; e < EE; e++) {
            float z = p[e];
            if (z > m1) { m2 = m1; b2 = b1; m1 = z; b1 = e; }
            else if (z > m2) { m2 = z; b2 = e; }
        }
        float e2 = __expf(m2 - m1);
        float inv = 1.0f / (1.0f + e2);
        float g1 = inv, g2 = e2 * inv;
        i1a[row] = b1; i2a[row] = b2; g1a[row] = g1; g2a[row] = g2;
        atomicAdd(&counts[b1], 1);
        atomicAdd(&counts[b2], 1);
        if (write_extras) {
            float2 iv; iv.x = (float)b1; iv.y = (float)b2;
            *(float2*)(out + IDX_OFF + (size_t)(row0 + row) * 2) = iv;
            float2 gv; gv.x = g1; gv.y = g2;
            *(float2*)(out + GATE_OFF + (size_t)(row0 + row) * 2) = gv;
        }
    }
    __syncthreads();

    // combine tensor (float4 coalesced)
#pragma unroll
    for (int j = 0; j < 4; j++) {
        int chunk = tid + NT * j;          // 2048 float4
        int r = chunk >> 4, c4 = chunk & 15;
        int b1 = i1a[r], b2 = i2a[r];
        float G1 = g1a[r], G2 = g2a[r];
        int cc = c4 * 4;
        float4 v;
        v.x = (cc     == b1) ? G1 : ((cc     == b2) ? G2 : 0.0f);
        v.y = (cc + 1 == b1) ? G1 : ((cc + 1 == b2) ? G2 : 0.0f);
        v.z = (cc + 2 == b1) ? G1 : ((cc + 2 == b2) ? G2 : 0.0f);
        v.w = (cc + 3 == b1) ? G1 : ((cc + 3 == b2) ? G2 : 0.0f);
        *(float4*)(out + (size_t)(row0 + r) * EE + cc) = v;
    }

    if (write_extras && tid < EE) {
        int cnt = counts[tid];
        if (cnt > 0) atomicAdd(out + ACT_OFF + tid, (float)cnt);
    }
}

extern "C" void kernel_launch(void* const* d_in, const int* in_sizes, int n_in,
                              void* d_out, int out_size) {
    const float* x     = (const float*)d_in[0];
    const float* w     = (const float*)d_in[1];
    const float* noise = (const float*)d_in[2];
    float* out = (float*)d_out;

    const int write_extras = ((size_t)out_size >= FULL_OUT) ? 1 : 0;

    cudaFuncSetAttribute(router_mma_kernel,
                         cudaFuncAttributeMaxDynamicSharedMemorySize, SMEM_BYTES);

    prep_kernel<<<128, 256>>>(w, out, write_extras);
    router_mma_kernel<<<TT / BM, NT, SMEM_BYTES>>>(x, noise, out, write_extras);
}

// round 8
// speedup vs baseline: 1.0724x; 1.0724x over previous
#include <cuda_runtime.h>
#include <cuda_fp16.h>
#include <cstdint>

#define TT 16384
#define DD 2048
#define EE 64
#define NT1 256                // gemm kernel threads
#define NCH 32                 // chunks of K=32 per K-half

// ---- gemm smem layout (u32 offsets), per buffer: Ahi[128][20] Alo[128][20] B[2048]
#define A_ROW 20
#define A_PLANE (128 * A_ROW)          // 2560
#define BUF_U32 (2 * A_PLANE + 2048)   // 7168
#define AOFF(b, pl) ((b) * BUF_U32 + (pl) * A_PLANE)
#define BOFF(b)     ((b) * BUF_U32 + 2 * A_PLANE)
#define SMEM1_U32 (2 * BUF_U32)        // 14336
#define SMEM1_BYTES (SMEM1_U32 * 4)    // 57344 -> 2 CTAs/SM

// ---- output layout (floats) ----
#define IDX_OFF  ((size_t)TT * EE)
#define GATE_OFF (IDX_OFF + 2 * (size_t)TT)
#define ACT_OFF  (GATE_OFF + 2 * (size_t)TT)
#define FULL_OUT (ACT_OFF + EE)

// w pre-split to fp16 hi/lo, fragment-major: [k16-step 128][nb 8][lane 32] uint4
__device__ uint4 g_w_frag[128 * 8 * 32];
// partial scores per K-half
__device__ float g_part0[(size_t)TT * EE];
__device__ float g_part1[(size_t)TT * EE];

__device__ __forceinline__ uint32_t packh2(__half a, __half b) {
    uint32_t u;
    asm("mov.b32 %0, {%1, %2};" : "=r"(u) : "h"(__half_as_ushort(a)), "h"(__half_as_ushort(b)));
    return u;
}
__device__ __forceinline__ void split_f16(float x, __half& h, __half& l) {
    h = __float2half_rn(x);
    l = __float2half_rn(x - __half2float(h));
}
__device__ __forceinline__ void mma_f16(float* d, const uint32_t* a, uint32_t b0, uint32_t b1) {
    asm volatile(
        "mma.sync.aligned.m16n8k16.row.col.f32.f16.f16.f32 "
        "{%0,%1,%2,%3}, {%4,%5,%6,%7}, {%8,%9}, {%0,%1,%2,%3};"
        : "+f"(d[0]), "+f"(d[1]), "+f"(d[2]), "+f"(d[3])
        : "r"(a[0]), "r"(a[1]), "r"(a[2]), "r"(a[3]), "r"(b0), "r"(b1));
}

// ======================= prep: w -> fragment-major fp16 hi/lo =======================
__global__ void prep_kernel(const float* __restrict__ w, float* __restrict__ out, int we) {
    int t = blockIdx.x * 256 + threadIdx.x;   // 32768 threads
    int ks = t >> 8, rem = t & 255, nb = rem >> 5, l = rem & 31;
    int n = nb * 8 + (l >> 2), tig = l & 3;
    int k0 = ks * 16 + 2 * tig, k1 = k0 + 8;
    float w00 = w[(size_t)k0 * EE + n],       w01 = w[(size_t)(k0 + 1) * EE + n];
    float w10 = w[(size_t)k1 * EE + n],       w11 = w[(size_t)(k1 + 1) * EE + n];
    __half h00, l00, h01, l01, h10, l10, h11, l11;
    split_f16(w00, h00, l00); split_f16(w01, h01, l01);
    split_f16(w10, h10, l10); split_f16(w11, h11, l11);
    uint4 v;
    v.x = packh2(h00, h01);
    v.y = packh2(h10, h11);
    v.z = packh2(l00, l01);
    v.w = packh2(l10, l11);
    g_w_frag[t] = v;
    if (we && t < EE) out[ACT_OFF + t] = 0.0f;
}

// ======================= gemm: 256 CTAs, each = 128 rows x one K-half =======================
__global__ __launch_bounds__(NT1, 2)
void gemm_kernel(const float* __restrict__ x) {
    extern __shared__ uint32_t smu[];
    const int tid = threadIdx.x;
    const int wid = tid >> 5;
    const int lid = tid & 31;
    const int g   = lid >> 2;
    const int t4  = lid & 3;
    const int half = blockIdx.x & 1;
    const int row0 = (blockIdx.x >> 1) * 128;
    const int rb   = wid * 16;         // warp rows rb..rb+15

    const size_t xko = (size_t)half * 1024;
    const int wfb = half * 64;         // first k16-step of this half

    float acc[8][4];
#pragma unroll
    for (int nb = 0; nb < 8; nb++)
#pragma unroll
        for (int i = 0; i < 4; i++) acc[nb][i] = 0.0f;

    // ---- produce chunk 0 ----
    {
        uint32_t* Ah = smu + AOFF(0, 0);
        uint32_t* Al = smu + AOFF(0, 1);
#pragma unroll
        for (int j = 0; j < 4; j++) {
            int flat = tid + NT1 * j;              // 1024 float4 of x tile
            int r = flat >> 3, kc = flat & 7;
            float4 v = *(const float4*)(x + (size_t)(row0 + r) * DD + xko + kc * 4);
            __half hx, lx, hy, ly, hz, lz, hw, lw;
            split_f16(v.x, hx, lx); split_f16(v.y, hy, ly);
            split_f16(v.z, hz, lz); split_f16(v.w, hw, lw);
            *(uint2*)(Ah + r * A_ROW + kc * 2) = make_uint2(packh2(hx, hy), packh2(hz, hw));
            *(uint2*)(Al + r * A_ROW + kc * 2) = make_uint2(packh2(lx, ly), packh2(lz, lw));
        }
        uint4* Bs = (uint4*)(smu + BOFF(0));
        const uint4* Bg = g_w_frag + (size_t)wfb * 256;
#pragma unroll
        for (int j = 0; j < 2; j++) Bs[tid + NT1 * j] = Bg[tid + NT1 * j];
    }
    __syncthreads();

    int buf = 0;
    for (int c = 0; c < NCH; ++c) {
        const bool more = (c + 1 < NCH);
        float4 xr[4];
        uint4  br[2];
        if (more) {
            const size_t kb = xko + (size_t)(c + 1) * 32;
#pragma unroll
            for (int j = 0; j < 4; j++) {
                int flat = tid + NT1 * j;
                int r = flat >> 3, kc = flat & 7;
                xr[j] = *(const float4*)(x + (size_t)(row0 + r) * DD + kb + kc * 4);
            }
            const uint4* Bg = g_w_frag + (size_t)(wfb + (c + 1) * 2) * 256;
#pragma unroll
            for (int j = 0; j < 2; j++) br[j] = Bg[tid + NT1 * j];
        }

        // ---- MMA on current buffer ----
        const uint32_t* Ah = smu + AOFF(buf, 0);
        const uint32_t* Al = smu + AOFF(buf, 1);
        const uint4*    Bs = (const uint4*)(smu + BOFF(buf));
#pragma unroll
        for (int ks = 0; ks < 2; ks++) {
            const int o = ks * 8 + t4;
            const int r = rb + g;
            uint32_t ah[4], al[4];
            ah[0] = Ah[r * A_ROW + o];
            ah[1] = Ah[(r + 8) * A_ROW + o];
            ah[2] = Ah[r * A_ROW + o + 4];
            ah[3] = Ah[(r + 8) * A_ROW + o + 4];
            al[0] = Al[r * A_ROW + o];
            al[1] = Al[(r + 8) * A_ROW + o];
            al[2] = Al[r * A_ROW + o + 4];
            al[3] = Al[(r + 8) * A_ROW + o + 4];
            uint4 bv[8];
#pragma unroll
            for (int nb = 0; nb < 8; nb++) bv[nb] = Bs[(ks * 8 + nb) * 32 + lid];
#pragma unroll
            for (int nb = 0; nb < 8; nb++) mma_f16(acc[nb], ah, bv[nb].x, bv[nb].y);  // h*h
#pragma unroll
            for (int nb = 0; nb < 8; nb++) mma_f16(acc[nb], ah, bv[nb].z, bv[nb].w);  // h*l
#pragma unroll
            for (int nb = 0; nb < 8; nb++) mma_f16(acc[nb], al, bv[nb].x, bv[nb].y);  // l*h
        }
        __syncthreads();

        if (more) {
            const int nbuf = buf ^ 1;
            uint32_t* Ahn = smu + AOFF(nbuf, 0);
            uint32_t* Aln = smu + AOFF(nbuf, 1);
#pragma unroll
            for (int j = 0; j < 4; j++) {
                int flat = tid + NT1 * j;
                int r = flat >> 3, kc = flat & 7;
                float4 v = xr[j];
                __half hx, lx, hy, ly, hz, lz, hw, lw;
                split_f16(v.x, hx, lx); split_f16(v.y, hy, ly);
                split_f16(v.z, hz, lz); split_f16(v.w, hw, lw);
                *(uint2*)(Ahn + r * A_ROW + kc * 2) = make_uint2(packh2(hx, hy), packh2(hz, hw));
                *(uint2*)(Aln + r * A_ROW + kc * 2) = make_uint2(packh2(lx, ly), packh2(lz, lw));
            }
            uint4* Bsn = (uint4*)(smu + BOFF(nbuf));
#pragma unroll
            for (int j = 0; j < 2; j++) Bsn[tid + NT1 * j] = br[j];
            __syncthreads();
            buf = nbuf;
        }
    }

    // ---- write partial scores ----
    float* part = half ? g_part1 : g_part0;
    const int r0 = row0 + rb + g;
#pragma unroll
    for (int nb = 0; nb < 8; nb++) {
        int cc = nb * 8 + t4 * 2;
        float2 v0; v0.x = acc[nb][0]; v0.y = acc[nb][1];
        float2 v1; v1.x = acc[nb][2]; v1.y = acc[nb][3];
        *(float2*)(part + (size_t)r0 * EE + cc)       = v0;
        *(float2*)(part + (size_t)(r0 + 8) * EE + cc) = v1;
    }
}

// ======================= finish: sum halves + noise, top-2, outputs =======================
#define SC2 66
__global__ __launch_bounds__(256)
void finish_kernel(const float* __restrict__ noise, float* __restrict__ out, int write_extras) {
    __shared__ float sc[64 * SC2];
    __shared__ int counts[EE];
    __shared__ int i1a[64], i2a[64];
    __shared__ float g1a[64], g2a[64];

    const int tid = threadIdx.x;
    const int row0 = blockIdx.x * 64;
    const size_t base4 = (size_t)row0 * 16;       // float4 index base

    const float4* p0 = (const float4*)g_part0;
    const float4* p1 = (const float4*)g_part1;
    const float4* nz = (const float4*)noise;

#pragma unroll
    for (int j = 0; j < 4; j++) {
        int idx = tid + 256 * j;                  // 1024 float4 = 64 rows x 16
        int r = idx >> 4, c4 = idx & 15;
        float4 a = p0[base4 + idx];
        float4 b = p1[base4 + idx];
        float4 n = nz[base4 + idx];
        float* d = sc + r * SC2 + c4 * 4;
        d[0] = a.x + b.x + n.x;
        d[1] = a.y + b.y + n.y;
        d[2] = a.z + b.z + n.z;
        d[3] = a.w + b.w + n.w;
    }
    if (tid < EE) counts[tid] = 0;
    __syncthreads();

    if (tid < 64) {
        const int row = tid;
        const float* p = sc + row * SC2;
        float m1 = -3.402823466e38f, m2 = -3.402823466e38f;
        int b1 = 0, b2 = 0;
#pragma unroll
        for (int e = 0; e < EE; e++) {
            float z = p[e];
            if (z > m1) { m2 = m1; b2 = b1; m1 = z; b1 = e; }
            else if (z > m2) { m2 = z; b2 = e; }
        }
        float e2 = __expf(m2 - m1);
        float inv = 1.0f / (1.0f + e2);
        float g1 = inv, g2 = e2 * inv;
        i1a[row] = b1; i2a[row] = b2; g1a[row] = g1; g2a[row] = g2;
        atomicAdd(&counts[b1], 1);
        atomicAdd(&counts[b2], 1);
        if (write_extras) {
            float2 iv; iv.x = (float)b1; iv.y = (float)b2;
            *(float2*)(out + IDX_OFF + (size_t)(row0 + row) * 2) = iv;
            float2 gv; gv.x = g1; gv.y = g2;
            *(float2*)(out + GATE_OFF + (size_t)(row0 + row) * 2) = gv;
        }
    }
    __syncthreads();

#pragma unroll
    for (int j = 0; j < 4; j++) {
        int idx = tid + 256 * j;                  // 1024 float4
        int r = idx >> 4, c4 = idx & 15;
        int b1 = i1a[r], b2 = i2a[r];
        float G1 = g1a[r], G2 = g2a[r];
        int cc = c4 * 4;
        float4 v;
        v.x = (cc     == b1) ? G1 : ((cc     == b2) ? G2 : 0.0f);
        v.y = (cc + 1 == b1) ? G1 : ((cc + 1 == b2) ? G2 : 0.0f);
        v.z = (cc + 2 == b1) ? G1 : ((cc + 2 == b2) ? G2 : 0.0f);
        v.w = (cc + 3 == b1) ? G1 : ((cc + 3 == b2) ? G2 : 0.0f);
        *(float4*)(out + (size_t)(row0 + r) * EE + cc) = v;
    }

    if (write_extras && tid < EE) {
        int cnt = counts[tid];
        if (cnt > 0) atomicAdd(out + ACT_OFF + tid, (float)cnt);
    }
}

extern "C" void kernel_launch(void* const* d_in, const int* in_sizes, int n_in,
                              void* d_out, int out_size) {
    const float* x     = (const float*)d_in[0];
    const float* w     = (const float*)d_in[1];
    const float* noise = (const float*)d_in[2];
    float* out = (float*)d_out;

    const int write_extras = ((size_t)out_size >= FULL_OUT) ? 1 : 0;

    cudaFuncSetAttribute(gemm_kernel,
                         cudaFuncAttributeMaxDynamicSharedMemorySize, SMEM1_BYTES);

    prep_kernel<<<128, 256>>>(w, out, write_extras);
    gemm_kernel<<<256, NT1, SMEM1_BYTES>>>(x);
    finish_kernel<<<256, 256>>>(noise, out, write_extras);
}